// round 3
// baseline (speedup 1.0000x reference)
#include <cuda_runtime.h>
#include <math.h>

// ---------------------------------------------------------------------------
// Problem constants
// ---------------------------------------------------------------------------
#define B_   4
#define S_   1024
#define D_   1024
#define H_   16
#define DK_  64
#define DFF_ 4096
#define ROWS_ (B_ * S_)   // 4096

// ---------------------------------------------------------------------------
// Scratch (device globals — no allocation allowed)
// ---------------------------------------------------------------------------
__device__ float g_xn [ROWS_ * D_];
__device__ float g_q  [ROWS_ * D_];
__device__ float g_k  [ROWS_ * D_];
__device__ float g_v  [ROWS_ * D_];
__device__ float g_ctx[ROWS_ * D_];
__device__ float g_xn2[ROWS_ * D_];
__device__ float g_ffh[(size_t)ROWS_ * DFF_];

// ---------------------------------------------------------------------------
// LayerNorm: scalar alpha/beta, torch std (ddof=1), eps added to std.
// One block per row (D=1024), 256 threads, 4 floats/thread in registers.
// ---------------------------------------------------------------------------
__global__ __launch_bounds__(256)
void ln_kernel(const float* __restrict__ x,
               const float* __restrict__ alpha,
               const float* __restrict__ beta,
               float* __restrict__ out)
{
    __shared__ float sbuf[8];
    const int row = blockIdx.x;
    const int tid = threadIdx.x;
    const float* xr = x + (size_t)row * D_;
    float4 xv = ((const float4*)xr)[tid];

    // --- mean ---
    float s = xv.x + xv.y + xv.z + xv.w;
    const int lane = tid & 31, w = tid >> 5;
    #pragma unroll
    for (int o = 16; o; o >>= 1) s += __shfl_xor_sync(0xffffffffu, s, o);
    if (lane == 0) sbuf[w] = s;
    __syncthreads();
    if (w == 0) {
        float t = (lane < 8) ? sbuf[lane] : 0.f;
        #pragma unroll
        for (int o = 4; o; o >>= 1) t += __shfl_xor_sync(0xffffffffu, t, o);
        if (lane == 0) sbuf[0] = t;
    }
    __syncthreads();
    const float mean = sbuf[0] * (1.0f / (float)D_);
    __syncthreads();

    // --- variance (two-pass, ddof=1) ---
    float d0 = xv.x - mean, d1 = xv.y - mean, d2 = xv.z - mean, d3 = xv.w - mean;
    float q = d0*d0 + d1*d1 + d2*d2 + d3*d3;
    #pragma unroll
    for (int o = 16; o; o >>= 1) q += __shfl_xor_sync(0xffffffffu, q, o);
    if (lane == 0) sbuf[w] = q;
    __syncthreads();
    if (w == 0) {
        float t = (lane < 8) ? sbuf[lane] : 0.f;
        #pragma unroll
        for (int o = 4; o; o >>= 1) t += __shfl_xor_sync(0xffffffffu, t, o);
        if (lane == 0) sbuf[0] = t;
    }
    __syncthreads();
    const float var = sbuf[0] * (1.0f / (float)(D_ - 1));
    const float stdv = sqrtf(var);
    const float a = alpha[0], b = beta[0];
    const float inv = a / (stdv + 1e-6f);

    float4 ov;
    ov.x = d0 * inv + b;
    ov.y = d1 * inv + b;
    ov.z = d2 * inv + b;
    ov.w = d3 * inv + b;
    ((float4*)(out + (size_t)row * D_))[tid] = ov;
}

// ---------------------------------------------------------------------------
// SGEMM: C[M,N] = epilogue(A[M,K] @ W[K,N] + bias[N])
//   EPI 0: none    1: relu    2: + res[M,N] (res may alias C)
// 128x128 tile, BK=8, 8x8 per thread, 256 threads.
// M,N,K must be multiples of 128/128/8 (they are here).
// ---------------------------------------------------------------------------
template<int EPI>
__global__ __launch_bounds__(256)
void sgemm_kernel(const float* __restrict__ A, const float* __restrict__ W,
                  const float* __restrict__ bias, const float* __restrict__ res,
                  float* __restrict__ C, int M, int N, int K)
{
    __shared__ float As[8][128];
    __shared__ float Bs[8][128];

    const int bm = blockIdx.y * 128;
    const int bn = blockIdx.x * 128;
    const int tid = threadIdx.x;

    const int arow = tid >> 1;            // 0..127
    const int acol = (tid & 1) * 4;       // 0 or 4
    const int brow = tid >> 5;            // 0..7
    const int bcol = (tid & 31) * 4;      // 0..124

    const int tx = tid & 15, ty = tid >> 4;
    const int crow = ty * 8, ccol = tx * 8;

    float acc[8][8];
    #pragma unroll
    for (int i = 0; i < 8; i++)
        #pragma unroll
        for (int j = 0; j < 8; j++) acc[i][j] = 0.f;

    const float* Aptr = A + (size_t)(bm + arow) * K + acol;
    const float* Bptr = W + (size_t)brow * N + bn + bcol;

    for (int kt = 0; kt < K; kt += 8) {
        float4 av = *(const float4*)(Aptr + kt);
        float4 bv = *(const float4*)(Bptr + (size_t)kt * N);
        As[acol + 0][arow] = av.x;
        As[acol + 1][arow] = av.y;
        As[acol + 2][arow] = av.z;
        As[acol + 3][arow] = av.w;
        *(float4*)&Bs[brow][bcol] = bv;
        __syncthreads();

        #pragma unroll
        for (int kk = 0; kk < 8; kk++) {
            float a[8], b[8];
            *(float4*)(a)     = *(const float4*)&As[kk][crow];
            *(float4*)(a + 4) = *(const float4*)&As[kk][crow + 4];
            *(float4*)(b)     = *(const float4*)&Bs[kk][ccol];
            *(float4*)(b + 4) = *(const float4*)&Bs[kk][ccol + 4];
            #pragma unroll
            for (int i = 0; i < 8; i++)
                #pragma unroll
                for (int j = 0; j < 8; j++)
                    acc[i][j] = fmaf(a[i], b[j], acc[i][j]);
        }
        __syncthreads();
    }

    // epilogue
    #pragma unroll
    for (int i = 0; i < 8; i++) {
        const size_t base = (size_t)(bm + crow + i) * N + bn + ccol;
        #pragma unroll
        for (int j0 = 0; j0 < 8; j0 += 4) {
            float4 o;
            o.x = acc[i][j0 + 0] + bias[bn + ccol + j0 + 0];
            o.y = acc[i][j0 + 1] + bias[bn + ccol + j0 + 1];
            o.z = acc[i][j0 + 2] + bias[bn + ccol + j0 + 2];
            o.w = acc[i][j0 + 3] + bias[bn + ccol + j0 + 3];
            if (EPI == 1) {
                o.x = fmaxf(o.x, 0.f); o.y = fmaxf(o.y, 0.f);
                o.z = fmaxf(o.z, 0.f); o.w = fmaxf(o.w, 0.f);
            }
            if (EPI == 2) {
                float4 rv = *(const float4*)(res + base + j0);
                o.x += rv.x; o.y += rv.y; o.z += rv.z; o.w += rv.w;
            }
            *(float4*)(C + base + j0) = o;
        }
    }
}

// ---------------------------------------------------------------------------
// Flash-style attention. Grid: (q_tiles=16, H=16, B=4). 256 threads.
// q,k,v are in (B,S,D) layout; head h occupies cols [h*64, h*64+64).
// Thread t owns q-row r = t&63 and 16 cols/dims c0 = (t>>6)*16.
// SMEM: Qs (transposed [dk][r]), KP (K as [c][dk], reused as P [c][r]),
//       Vs ([c][d]), red ([4][64]).  Total 50176 bytes (dynamic).
// ---------------------------------------------------------------------------
#define ATTN_SMEM_FLOATS (4096 * 3 + 256)
#define ATTN_SMEM_BYTES  (ATTN_SMEM_FLOATS * 4)

__global__ __launch_bounds__(256)
void attn_kernel(const float* __restrict__ q, const float* __restrict__ k,
                 const float* __restrict__ v, const int* __restrict__ mask,
                 float* __restrict__ ctx)
{
    extern __shared__ float sm[];
    float* Qs  = sm;            // 4096
    float* KP  = sm + 4096;     // 4096
    float* Vs  = sm + 8192;     // 4096
    float* red = sm + 12288;    // 256

    const int tid = threadIdx.x;
    const int r   = tid & 63;
    const int cg  = tid >> 6;
    const int c0  = cg * 16;
    const int qt  = blockIdx.x, h = blockIdx.y, b = blockIdx.z;

    // load Q tile, store transposed Qs[dk][r]
    {
        const float* qp = q + ((size_t)(b * S_ + qt * 64 + r)) * D_ + h * 64 + c0;
        #pragma unroll
        for (int j = 0; j < 16; j++) Qs[(c0 + j) * 64 + r] = qp[j];
    }

    float O[16];
    #pragma unroll
    for (int j = 0; j < 16; j++) O[j] = 0.f;
    float m = -1e30f, l = 0.f;

    const int* mrow = mask + b * S_;

    for (int kt = 0; kt < 16; kt++) {
        __syncthreads();  // previous tile consumers done; Q visible on iter 0
        // load K,V tile rows (row = kt*64 + r), cols c0..c0+15
        {
            const float* kp = k + ((size_t)(b * S_ + kt * 64 + r)) * D_ + h * 64 + c0;
            const float* vp = v + ((size_t)(b * S_ + kt * 64 + r)) * D_ + h * 64 + c0;
            #pragma unroll
            for (int j = 0; j < 16; j += 4) {
                float4 kv = *(const float4*)(kp + j);
                float4 vv = *(const float4*)(vp + j);
                *(float4*)&KP[r * 64 + c0 + j] = kv;
                *(float4*)&Vs[r * 64 + c0 + j] = vv;
            }
        }
        __syncthreads();

        // scores: s[j] = sum_dk Q[r][dk] * K[c0+j][dk]
        float s[16];
        #pragma unroll
        for (int j = 0; j < 16; j++) s[j] = 0.f;
        for (int kk = 0; kk < 64; kk++) {
            float qv = Qs[kk * 64 + r];
            #pragma unroll
            for (int j = 0; j < 16; j++)
                s[j] = fmaf(qv, KP[(c0 + j) * 64 + kk], s[j]);
        }

        float pm = -1e30f;
        #pragma unroll
        for (int j = 0; j < 16; j++) {
            s[j] *= 0.125f;                          // 1/sqrt(64)
            if (mrow[kt * 64 + c0 + j] == 0) s[j] = -1e9f;
            pm = fmaxf(pm, s[j]);
        }
        red[cg * 64 + r] = pm;
        __syncthreads();   // also orders: K reads done before P overwrites KP

        float mn = fmaxf(fmaxf(red[r], red[64 + r]), fmaxf(red[128 + r], red[192 + r]));
        mn = fmaxf(mn, m);
        const float alpha = expf(m - mn);

        float psum = 0.f;
        #pragma unroll
        for (int j = 0; j < 16; j++) {
            float p = expf(s[j] - mn);
            psum += p;
            KP[(c0 + j) * 64 + r] = p;               // P transposed [c][r]
        }
        __syncthreads();   // red max reads done; P writes visible
        red[cg * 64 + r] = psum;
        __syncthreads();
        const float rs = red[r] + red[64 + r] + red[128 + r] + red[192 + r];

        l = l * alpha + rs;
        #pragma unroll
        for (int j = 0; j < 16; j++) O[j] *= alpha;

        // ctx: O[r][c0+j] += sum_c P[r][c] * V[c][c0+j]
        for (int cc = 0; cc < 64; cc++) {
            float p = KP[cc * 64 + r];
            #pragma unroll
            for (int j = 0; j < 16; j++)
                O[j] = fmaf(p, Vs[cc * 64 + c0 + j], O[j]);
        }
        m = mn;
    }

    const float inv = 1.f / l;
    float* op = ctx + ((size_t)(b * S_ + qt * 64 + r)) * D_ + h * 64 + c0;
    #pragma unroll
    for (int j = 0; j < 16; j++) op[j] = O[j] * inv;
}

// ---------------------------------------------------------------------------
// Launch
// ---------------------------------------------------------------------------
extern "C" void kernel_launch(void* const* d_in, const int* in_sizes, int n_in,
                              void* d_out, int out_size)
{
    const float* x    = (const float*)d_in[0];
    const int*   mask = (const int*)  d_in[1];
    const float* wq   = (const float*)d_in[2];
    const float* bq   = (const float*)d_in[3];
    const float* wk   = (const float*)d_in[4];
    const float* bk   = (const float*)d_in[5];
    const float* wv   = (const float*)d_in[6];
    const float* bv   = (const float*)d_in[7];
    const float* wo   = (const float*)d_in[8];
    const float* bo   = (const float*)d_in[9];
    const float* w1   = (const float*)d_in[10];
    const float* b1   = (const float*)d_in[11];
    const float* w2   = (const float*)d_in[12];
    const float* b2   = (const float*)d_in[13];
    const float* a1   = (const float*)d_in[14];
    const float* be1  = (const float*)d_in[15];
    const float* a2   = (const float*)d_in[16];
    const float* be2  = (const float*)d_in[17];
    float* out = (float*)d_out;

    float *xn, *q, *k, *v, *ctx, *xn2, *ffh;
    cudaGetSymbolAddress((void**)&xn,  g_xn);
    cudaGetSymbolAddress((void**)&q,   g_q);
    cudaGetSymbolAddress((void**)&k,   g_k);
    cudaGetSymbolAddress((void**)&v,   g_v);
    cudaGetSymbolAddress((void**)&ctx, g_ctx);
    cudaGetSymbolAddress((void**)&xn2, g_xn2);
    cudaGetSymbolAddress((void**)&ffh, g_ffh);

    cudaFuncSetAttribute(attn_kernel,
                         cudaFuncAttributeMaxDynamicSharedMemorySize,
                         ATTN_SMEM_BYTES);

    const dim3 gemm_d (D_   / 128, ROWS_ / 128);   // (8, 32)
    const dim3 gemm_ff(DFF_ / 128, ROWS_ / 128);   // (32, 32)

    // 1) pre-norm 1
    ln_kernel<<<ROWS_, 256>>>(x, a1, be1, xn);

    // 2) Q/K/V projections
    sgemm_kernel<0><<<gemm_d, 256>>>(xn, wq, bq, nullptr, q, ROWS_, D_, D_);
    sgemm_kernel<0><<<gemm_d, 256>>>(xn, wk, bk, nullptr, k, ROWS_, D_, D_);
    sgemm_kernel<0><<<gemm_d, 256>>>(xn, wv, bv, nullptr, v, ROWS_, D_, D_);

    // 3) attention
    attn_kernel<<<dim3(S_ / 64, H_, B_), 256, ATTN_SMEM_BYTES>>>(q, k, v, mask, ctx);

    // 4) output projection + residual 1 -> out = x + ctx@wo + bo
    sgemm_kernel<2><<<gemm_d, 256>>>(ctx, wo, bo, x, out, ROWS_, D_, D_);

    // 5) pre-norm 2
    ln_kernel<<<ROWS_, 256>>>(out, a2, be2, xn2);

    // 6) FFN up + relu
    sgemm_kernel<1><<<gemm_ff, 256>>>(xn2, w1, b1, nullptr, ffh, ROWS_, DFF_, D_);

    // 7) FFN down + residual 2 (in-place residual on out)
    sgemm_kernel<2><<<gemm_d, 256>>>(ffh, w2, b2, out, out, ROWS_, D_, DFF_);
}

// round 10
// speedup vs baseline: 1.7310x; 1.7310x over previous
#include <cuda_runtime.h>
#include <cuda_bf16.h>
#include <math.h>
#include <stdint.h>

// ---------------------------------------------------------------------------
// Problem constants
// ---------------------------------------------------------------------------
#define B_   4
#define S_   1024
#define D_   1024
#define H_   16
#define DK_  64
#define DFF_ 4096
#define ROWS_ (B_ * S_)   // 4096

// ---------------------------------------------------------------------------
// Scratch (device globals — no allocation allowed)
// ---------------------------------------------------------------------------
__device__ float g_q  [ROWS_ * D_];
__device__ float g_k  [ROWS_ * D_];
__device__ float g_v  [ROWS_ * D_];
__device__ float g_ctx[ROWS_ * D_];

__device__ __nv_bfloat16 g_xn_h [ROWS_ * D_],  g_xn_l [ROWS_ * D_];
__device__ __nv_bfloat16 g_xn2_h[ROWS_ * D_],  g_xn2_l[ROWS_ * D_];
__device__ __nv_bfloat16 g_ctx_h[ROWS_ * D_],  g_ctx_l[ROWS_ * D_];
__device__ __nv_bfloat16 g_ffh_h[(size_t)ROWS_ * DFF_], g_ffh_l[(size_t)ROWS_ * DFF_];

// transposed weights [N, K] hi/lo
__device__ __nv_bfloat16 g_wqt_h[D_ * D_], g_wqt_l[D_ * D_];
__device__ __nv_bfloat16 g_wkt_h[D_ * D_], g_wkt_l[D_ * D_];
__device__ __nv_bfloat16 g_wvt_h[D_ * D_], g_wvt_l[D_ * D_];
__device__ __nv_bfloat16 g_wot_h[D_ * D_], g_wot_l[D_ * D_];
__device__ __nv_bfloat16 g_w1t_h[(size_t)DFF_ * D_], g_w1t_l[(size_t)DFF_ * D_];
__device__ __nv_bfloat16 g_w2t_h[(size_t)D_ * DFF_], g_w2t_l[(size_t)D_ * DFF_];

__device__ __forceinline__ void split_hl(float v, __nv_bfloat16& h, __nv_bfloat16& l) {
    h = __float2bfloat16(v);
    l = __float2bfloat16(v - __bfloat162float(h));
}

__device__ __forceinline__ uint32_t smem_u32(const void* p) {
    uint32_t a;
    asm("{ .reg .u64 t; cvta.to.shared.u64 t, %1; cvt.u32.u64 %0, t; }"
        : "=r"(a) : "l"(p));
    return a;
}
__device__ __forceinline__ void cp16(uint32_t dst, const void* src) {
    asm volatile("cp.async.cg.shared.global [%0], [%1], 16;"
                 :: "r"(dst), "l"(src) : "memory");
}
#define CP_COMMIT() asm volatile("cp.async.commit_group;" ::: "memory")
#define CP_WAIT(n)  asm volatile("cp.async.wait_group %0;" :: "n"(n) : "memory")

// bf16 warp MMA: D(16x8 f32) += A(16x16 bf16, row) * B(16x8 bf16, col)
__device__ __forceinline__ void mma_bf16(float* c, const uint32_t* a, const uint32_t* b) {
    asm volatile(
        "mma.sync.aligned.m16n8k16.row.col.f32.bf16.bf16.f32 "
        "{%0,%1,%2,%3}, {%4,%5,%6,%7}, {%8,%9}, {%0,%1,%2,%3};"
        : "+f"(c[0]), "+f"(c[1]), "+f"(c[2]), "+f"(c[3])
        : "r"(a[0]), "r"(a[1]), "r"(a[2]), "r"(a[3]), "r"(b[0]), "r"(b[1]));
}

// ---------------------------------------------------------------------------
// LayerNorm (torch semantics: ddof=1 std, eps on std, scalar alpha/beta),
// writing hi/lo bf16 split directly. One block per row, 256 threads.
// ---------------------------------------------------------------------------
__global__ __launch_bounds__(256)
void ln_hilo_kernel(const float* __restrict__ x,
                    const float* __restrict__ alpha,
                    const float* __restrict__ beta,
                    __nv_bfloat16* __restrict__ oh,
                    __nv_bfloat16* __restrict__ ol)
{
    __shared__ float sbuf[8];
    const int row = blockIdx.x;
    const int tid = threadIdx.x;
    float4 xv = ((const float4*)(x + (size_t)row * D_))[tid];

    float s = xv.x + xv.y + xv.z + xv.w;
    const int lane = tid & 31, w = tid >> 5;
    #pragma unroll
    for (int o = 16; o; o >>= 1) s += __shfl_xor_sync(0xffffffffu, s, o);
    if (lane == 0) sbuf[w] = s;
    __syncthreads();
    if (w == 0) {
        float t = (lane < 8) ? sbuf[lane] : 0.f;
        #pragma unroll
        for (int o = 4; o; o >>= 1) t += __shfl_xor_sync(0xffffffffu, t, o);
        if (lane == 0) sbuf[0] = t;
    }
    __syncthreads();
    const float mean = sbuf[0] * (1.0f / (float)D_);
    __syncthreads();

    float d0 = xv.x - mean, d1 = xv.y - mean, d2 = xv.z - mean, d3 = xv.w - mean;
    float q = d0*d0 + d1*d1 + d2*d2 + d3*d3;
    #pragma unroll
    for (int o = 16; o; o >>= 1) q += __shfl_xor_sync(0xffffffffu, q, o);
    if (lane == 0) sbuf[w] = q;
    __syncthreads();
    if (w == 0) {
        float t = (lane < 8) ? sbuf[lane] : 0.f;
        #pragma unroll
        for (int o = 4; o; o >>= 1) t += __shfl_xor_sync(0xffffffffu, t, o);
        if (lane == 0) sbuf[0] = t;
    }
    __syncthreads();
    const float stdv = sqrtf(sbuf[0] * (1.0f / (float)(D_ - 1)));
    const float inv = alpha[0] / (stdv + 1e-6f);
    const float b = beta[0];

    float v0 = d0 * inv + b, v1 = d1 * inv + b, v2 = d2 * inv + b, v3 = d3 * inv + b;
    __nv_bfloat16 h0, h1, h2, h3, l0, l1, l2, l3;
    split_hl(v0, h0, l0); split_hl(v1, h1, l1);
    split_hl(v2, h2, l2); split_hl(v3, h3, l3);
    ushort4 hv, lv;
    hv.x = __bfloat16_as_ushort(h0); hv.y = __bfloat16_as_ushort(h1);
    hv.z = __bfloat16_as_ushort(h2); hv.w = __bfloat16_as_ushort(h3);
    lv.x = __bfloat16_as_ushort(l0); lv.y = __bfloat16_as_ushort(l1);
    lv.z = __bfloat16_as_ushort(l2); lv.w = __bfloat16_as_ushort(l3);
    ((ushort4*)(oh + (size_t)row * D_))[tid] = hv;
    ((ushort4*)(ol + (size_t)row * D_))[tid] = lv;
}

// ---------------------------------------------------------------------------
// fp32 -> hi/lo bf16 elementwise converter (attention context output)
// ---------------------------------------------------------------------------
__global__ __launch_bounds__(256)
void f32_to_hilo_kernel(const float* __restrict__ in,
                        __nv_bfloat16* __restrict__ oh,
                        __nv_bfloat16* __restrict__ ol, int n4)
{
    int i = blockIdx.x * blockDim.x + threadIdx.x;
    if (i >= n4) return;
    float4 v = ((const float4*)in)[i];
    __nv_bfloat16 h0,h1,h2,h3,l0,l1,l2,l3;
    split_hl(v.x,h0,l0); split_hl(v.y,h1,l1); split_hl(v.z,h2,l2); split_hl(v.w,h3,l3);
    ushort4 hv, lv;
    hv.x=__bfloat16_as_ushort(h0); hv.y=__bfloat16_as_ushort(h1);
    hv.z=__bfloat16_as_ushort(h2); hv.w=__bfloat16_as_ushort(h3);
    lv.x=__bfloat16_as_ushort(l0); lv.y=__bfloat16_as_ushort(l1);
    lv.z=__bfloat16_as_ushort(l2); lv.w=__bfloat16_as_ushort(l3);
    ((ushort4*)oh)[i] = hv;
    ((ushort4*)ol)[i] = lv;
}

// ---------------------------------------------------------------------------
// Weight convert + transpose: W[K,N] fp32 -> T_hi/T_lo [N,K] bf16.
// ---------------------------------------------------------------------------
__global__ __launch_bounds__(256)
void wconv_kernel(const float* __restrict__ W,
                  __nv_bfloat16* __restrict__ Th,
                  __nv_bfloat16* __restrict__ Tl, int K, int N)
{
    __shared__ float s[32][33];
    const int kb = blockIdx.y * 32, nb = blockIdx.x * 32;
    const int tx = threadIdx.x, ty = threadIdx.y;
    #pragma unroll
    for (int i = 0; i < 4; i++)
        s[ty + i*8][tx] = W[(size_t)(kb + ty + i*8) * N + nb + tx];
    __syncthreads();
    #pragma unroll
    for (int i = 0; i < 4; i++) {
        int n = nb + ty + i*8, k = kb + tx;
        float v = s[tx][ty + i*8];
        __nv_bfloat16 h, l;
        split_hl(v, h, l);
        Th[(size_t)n * K + k] = h;
        Tl[(size_t)n * K + k] = l;
    }
}

// ---------------------------------------------------------------------------
// bf16x3 tensor-core GEMM via mma.sync (HMMA — baseline PTX, works on
// compute_103 target):   C[M,N] = epi(A[M,K] @ W[K,N] + bias)
// A as hi/lo bf16 [M,K]; W transposed hi/lo bf16 [N,K].
// acc += Ahi*Bhi + Alo*Bhi + Ahi*Blo  (fp32 accumulate)
// 128x128 tile, BK=32, 8 warps (2x4), warp tile 64x32 (4x4 m16n8k16 frags).
// 2-stage cp.async pipeline; SMEM rows padded to 40 bf16 (conflict-free).
//   EPI 0: fp32 = acc + bias
//   EPI 1: hi/lo bf16 = relu(acc + bias)
//   EPI 2: fp32 = acc + bias + res   (res may alias C)
// ---------------------------------------------------------------------------
#define MT 128
#define NT 128
#define KT 32
#define STRIDE 40                      // bf16 per smem row (32 data + 8 pad)
#define TILE_E (MT * STRIDE)           // 5120 bf16 per subtile
#define STAGE_E (4 * TILE_E)           // Ah, Al, Bh, Bl
#define GEMM_SMEM (2 * STAGE_E * 2)    // bytes = 81920

__device__ __forceinline__ void issue_stage(
        uint32_t sdst_base,
        const __nv_bfloat16* __restrict__ Ah, const __nv_bfloat16* __restrict__ Al,
        const __nv_bfloat16* __restrict__ Bh, const __nv_bfloat16* __restrict__ Bl,
        int K, int k0, int bm, int bn, int tid)
{
    #pragma unroll
    for (int i = 0; i < 8; i++) {
        const int gid  = i * 256 + tid;
        const int tile = gid >> 9;        // 0:Ah 1:Al 2:Bh 3:Bl
        const int rem  = gid & 511;
        const int row  = rem >> 2;
        const int ch   = rem & 3;
        const __nv_bfloat16* base = (tile == 0) ? Ah : (tile == 1) ? Al
                                  : (tile == 2) ? Bh : Bl;
        const int grow = ((tile < 2) ? bm : bn) + row;
        const __nv_bfloat16* src = base + (size_t)grow * K + k0 + ch * 8;
        const uint32_t dst = sdst_base +
            (uint32_t)(tile * TILE_E + row * STRIDE + ch * 8) * 2;
        cp16(dst, src);
    }
}

template<int EPI>
__global__ __launch_bounds__(256)
void tc_gemm_kernel(const __nv_bfloat16* __restrict__ Ahi,
                    const __nv_bfloat16* __restrict__ Alo,
                    const __nv_bfloat16* __restrict__ Bhi,
                    const __nv_bfloat16* __restrict__ Blo,
                    const float* __restrict__ bias,
                    const float* __restrict__ res,
                    float* __restrict__ C,
                    __nv_bfloat16* __restrict__ Chi,
                    __nv_bfloat16* __restrict__ Clo,
                    int M, int N, int K)
{
    extern __shared__ char smraw[];
    __nv_bfloat16* sm = (__nv_bfloat16*)smraw;
    const uint32_t smb = smem_u32(smraw);

    const int tid  = threadIdx.x;
    const int wid  = tid >> 5, lane = tid & 31;
    const int gidq = lane >> 2, tig = lane & 3;   // groupID, threadInGroup
    const int wm   = wid >> 2, wn = wid & 3;      // 2 x 4 warp grid
    const int bm   = blockIdx.y * MT, bn = blockIdx.x * NT;

    float acc[4][4][4];
    #pragma unroll
    for (int i = 0; i < 4; i++)
        #pragma unroll
        for (int j = 0; j < 4; j++)
            #pragma unroll
            for (int r = 0; r < 4; r++) acc[i][j][r] = 0.f;

    const int NK = K / KT;

    issue_stage(smb, Ahi, Alo, Bhi, Blo, K, 0, bm, bn, tid);
    CP_COMMIT();

    for (int kt = 0; kt < NK; ++kt) {
        const int s = kt & 1;
        if (kt + 1 < NK) {
            issue_stage(smb + (uint32_t)(s ^ 1) * STAGE_E * 2,
                        Ahi, Alo, Bhi, Blo, K, (kt + 1) * KT, bm, bn, tid);
            CP_COMMIT();
            CP_WAIT(1);
        } else {
            CP_WAIT(0);
        }
        __syncthreads();

        const __nv_bfloat16* sa_h = sm + s * STAGE_E;
        const __nv_bfloat16* sa_l = sa_h + TILE_E;
        const __nv_bfloat16* sb_h = sa_h + 2 * TILE_E;
        const __nv_bfloat16* sb_l = sa_h + 3 * TILE_E;

        #pragma unroll
        for (int k2 = 0; k2 < KT; k2 += 16) {
            const int kc = k2 + tig * 2;
            uint32_t ah[4][4], bh[4][2], bl[4][2], al[4][4];

            #pragma unroll
            for (int mf = 0; mf < 4; mf++) {
                const int r0 = wm * 64 + mf * 16 + gidq;
                ah[mf][0] = *(const uint32_t*)(sa_h + r0 * STRIDE + kc);
                ah[mf][1] = *(const uint32_t*)(sa_h + (r0 + 8) * STRIDE + kc);
                ah[mf][2] = *(const uint32_t*)(sa_h + r0 * STRIDE + kc + 8);
                ah[mf][3] = *(const uint32_t*)(sa_h + (r0 + 8) * STRIDE + kc + 8);
            }
            #pragma unroll
            for (int nf = 0; nf < 4; nf++) {
                const int r0 = wn * 32 + nf * 8 + gidq;
                bh[nf][0] = *(const uint32_t*)(sb_h + r0 * STRIDE + kc);
                bh[nf][1] = *(const uint32_t*)(sb_h + r0 * STRIDE + kc + 8);
            }
            #pragma unroll
            for (int mf = 0; mf < 4; mf++)
                #pragma unroll
                for (int nf = 0; nf < 4; nf++)
                    mma_bf16(acc[mf][nf], ah[mf], bh[nf]);

            #pragma unroll
            for (int nf = 0; nf < 4; nf++) {
                const int r0 = wn * 32 + nf * 8 + gidq;
                bl[nf][0] = *(const uint32_t*)(sb_l + r0 * STRIDE + kc);
                bl[nf][1] = *(const uint32_t*)(sb_l + r0 * STRIDE + kc + 8);
            }
            #pragma unroll
            for (int mf = 0; mf < 4; mf++)
                #pragma unroll
                for (int nf = 0; nf < 4; nf++)
                    mma_bf16(acc[mf][nf], ah[mf], bl[nf]);

            #pragma unroll
            for (int mf = 0; mf < 4; mf++) {
                const int r0 = wm * 64 + mf * 16 + gidq;
                al[mf][0] = *(const uint32_t*)(sa_l + r0 * STRIDE + kc);
                al[mf][1] = *(const uint32_t*)(sa_l + (r0 + 8) * STRIDE + kc);
                al[mf][2] = *(const uint32_t*)(sa_l + r0 * STRIDE + kc + 8);
                al[mf][3] = *(const uint32_t*)(sa_l + (r0 + 8) * STRIDE + kc + 8);
            }
            #pragma unroll
            for (int mf = 0; mf < 4; mf++)
                #pragma unroll
                for (int nf = 0; nf < 4; nf++)
                    mma_bf16(acc[mf][nf], al[mf], bh[nf]);
        }
        __syncthreads();
    }

    // ---- epilogue ----
    #pragma unroll
    for (int mf = 0; mf < 4; mf++) {
        #pragma unroll
        for (int nf = 0; nf < 4; nf++) {
            const int r = bm + wm * 64 + mf * 16 + gidq;
            const int c = bn + wn * 32 + nf * 8 + tig * 2;
            const float b0 = __ldg(&bias[c]), b1 = __ldg(&bias[c + 1]);
            float v00 = acc[mf][nf][0] + b0, v01 = acc[mf][nf][1] + b1;
            float v10 = acc[mf][nf][2] + b0, v11 = acc[mf][nf][3] + b1;
            if (EPI == 1) {
                v00 = fmaxf(v00, 0.f); v01 = fmaxf(v01, 0.f);
                v10 = fmaxf(v10, 0.f); v11 = fmaxf(v11, 0.f);
                __nv_bfloat16 h, l;
                uint32_t hw, lw;
                split_hl(v00, h, l);
                hw = __bfloat16_as_ushort(h); lw = __bfloat16_as_ushort(l);
                split_hl(v01, h, l);
                hw |= (uint32_t)__bfloat16_as_ushort(h) << 16;
                lw |= (uint32_t)__bfloat16_as_ushort(l) << 16;
                *(uint32_t*)(Chi + (size_t)r * N + c) = hw;
                *(uint32_t*)(Clo + (size_t)r * N + c) = lw;
                split_hl(v10, h, l);
                hw = __bfloat16_as_ushort(h); lw = __bfloat16_as_ushort(l);
                split_hl(v11, h, l);
                hw |= (uint32_t)__bfloat16_as_ushort(h) << 16;
                lw |= (uint32_t)__bfloat16_as_ushort(l) << 16;
                *(uint32_t*)(Chi + (size_t)(r + 8) * N + c) = hw;
                *(uint32_t*)(Clo + (size_t)(r + 8) * N + c) = lw;
            } else {
                if (EPI == 2) {
                    float2 r0 = *(const float2*)(res + (size_t)r * N + c);
                    float2 r1 = *(const float2*)(res + (size_t)(r + 8) * N + c);
                    v00 += r0.x; v01 += r0.y; v10 += r1.x; v11 += r1.y;
                }
                float2 o0 = make_float2(v00, v01), o1 = make_float2(v10, v11);
                *(float2*)(C + (size_t)r * N + c) = o0;
                *(float2*)(C + (size_t)(r + 8) * N + c) = o1;
            }
        }
    }
}

// ---------------------------------------------------------------------------
// Flash-style attention (fp32). Grid: (q_tiles=16, H=16, B=4). 256 threads.
// ---------------------------------------------------------------------------
#define ATTN_SMEM_BYTES ((4096 * 3 + 256) * 4)

__global__ __launch_bounds__(256)
void attn_kernel(const float* __restrict__ q, const float* __restrict__ k,
                 const float* __restrict__ v, const int* __restrict__ mask,
                 float* __restrict__ ctx)
{
    extern __shared__ char smraw[];
    float* smf = (float*)smraw;
    float* Qs  = smf;
    float* KP  = smf + 4096;
    float* Vs  = smf + 8192;
    float* red = smf + 12288;

    const int tid = threadIdx.x;
    const int r   = tid & 63;
    const int cg  = tid >> 6;
    const int c0  = cg * 16;
    const int qt  = blockIdx.x, h = blockIdx.y, b = blockIdx.z;

    {
        const float* qp = q + ((size_t)(b * S_ + qt * 64 + r)) * D_ + h * 64 + c0;
        #pragma unroll
        for (int j = 0; j < 16; j++) Qs[(c0 + j) * 64 + r] = qp[j];
    }

    float O[16];
    #pragma unroll
    for (int j = 0; j < 16; j++) O[j] = 0.f;
    float m = -1e30f, l = 0.f;
    const int* mrow = mask + b * S_;

    for (int kt = 0; kt < 16; kt++) {
        __syncthreads();
        {
            const float* kp = k + ((size_t)(b * S_ + kt * 64 + r)) * D_ + h * 64 + c0;
            const float* vp = v + ((size_t)(b * S_ + kt * 64 + r)) * D_ + h * 64 + c0;
            #pragma unroll
            for (int j = 0; j < 16; j += 4) {
                float4 kv = *(const float4*)(kp + j);
                float4 vv = *(const float4*)(vp + j);
                *(float4*)&KP[r * 64 + c0 + j] = kv;
                *(float4*)&Vs[r * 64 + c0 + j] = vv;
            }
        }
        __syncthreads();

        float s[16];
        #pragma unroll
        for (int j = 0; j < 16; j++) s[j] = 0.f;
        for (int kk = 0; kk < 64; kk++) {
            float qv = Qs[kk * 64 + r];
            #pragma unroll
            for (int j = 0; j < 16; j++)
                s[j] = fmaf(qv, KP[(c0 + j) * 64 + kk], s[j]);
        }

        float pm = -1e30f;
        #pragma unroll
        for (int j = 0; j < 16; j++) {
            s[j] *= 0.125f;
            if (mrow[kt * 64 + c0 + j] == 0) s[j] = -1e9f;
            pm = fmaxf(pm, s[j]);
        }
        red[cg * 64 + r] = pm;
        __syncthreads();

        float mn = fmaxf(fmaxf(red[r], red[64 + r]), fmaxf(red[128 + r], red[192 + r]));
        mn = fmaxf(mn, m);
        const float alpha = expf(m - mn);

        float psum = 0.f;
        #pragma unroll
        for (int j = 0; j < 16; j++) {
            float p = expf(s[j] - mn);
            psum += p;
            KP[(c0 + j) * 64 + r] = p;
        }
        __syncthreads();
        red[cg * 64 + r] = psum;
        __syncthreads();
        const float rs = red[r] + red[64 + r] + red[128 + r] + red[192 + r];

        l = l * alpha + rs;
        #pragma unroll
        for (int j = 0; j < 16; j++) O[j] *= alpha;

        for (int cc = 0; cc < 64; cc++) {
            float p = KP[cc * 64 + r];
            #pragma unroll
            for (int j = 0; j < 16; j++)
                O[j] = fmaf(p, Vs[cc * 64 + c0 + j], O[j]);
        }
        m = mn;
    }

    const float inv = 1.f / l;
    float* op = ctx + ((size_t)(b * S_ + qt * 64 + r)) * D_ + h * 64 + c0;
    #pragma unroll
    for (int j = 0; j < 16; j++) op[j] = O[j] * inv;
}

// ---------------------------------------------------------------------------
// Launch
// ---------------------------------------------------------------------------
extern "C" void kernel_launch(void* const* d_in, const int* in_sizes, int n_in,
                              void* d_out, int out_size)
{
    const float* x    = (const float*)d_in[0];
    const int*   mask = (const int*)  d_in[1];
    const float* wq   = (const float*)d_in[2];
    const float* bq   = (const float*)d_in[3];
    const float* wk   = (const float*)d_in[4];
    const float* bk   = (const float*)d_in[5];
    const float* wv   = (const float*)d_in[6];
    const float* bv   = (const float*)d_in[7];
    const float* wo   = (const float*)d_in[8];
    const float* bo   = (const float*)d_in[9];
    const float* w1   = (const float*)d_in[10];
    const float* b1   = (const float*)d_in[11];
    const float* w2   = (const float*)d_in[12];
    const float* b2   = (const float*)d_in[13];
    const float* a1   = (const float*)d_in[14];
    const float* be1  = (const float*)d_in[15];
    const float* a2   = (const float*)d_in[16];
    const float* be2  = (const float*)d_in[17];
    float* out = (float*)d_out;

    float *q, *k, *v, *ctx;
    __nv_bfloat16 *xnh, *xnl, *xn2h, *xn2l, *ctxh, *ctxl, *ffhh, *ffhl;
    __nv_bfloat16 *wqth, *wqtl, *wkth, *wktl, *wvth, *wvtl, *woth, *wotl;
    __nv_bfloat16 *w1th, *w1tl, *w2th, *w2tl;
    cudaGetSymbolAddress((void**)&q,    g_q);
    cudaGetSymbolAddress((void**)&k,    g_k);
    cudaGetSymbolAddress((void**)&v,    g_v);
    cudaGetSymbolAddress((void**)&ctx,  g_ctx);
    cudaGetSymbolAddress((void**)&xnh,  g_xn_h);  cudaGetSymbolAddress((void**)&xnl,  g_xn_l);
    cudaGetSymbolAddress((void**)&xn2h, g_xn2_h); cudaGetSymbolAddress((void**)&xn2l, g_xn2_l);
    cudaGetSymbolAddress((void**)&ctxh, g_ctx_h); cudaGetSymbolAddress((void**)&ctxl, g_ctx_l);
    cudaGetSymbolAddress((void**)&ffhh, g_ffh_h); cudaGetSymbolAddress((void**)&ffhl, g_ffh_l);
    cudaGetSymbolAddress((void**)&wqth, g_wqt_h); cudaGetSymbolAddress((void**)&wqtl, g_wqt_l);
    cudaGetSymbolAddress((void**)&wkth, g_wkt_h); cudaGetSymbolAddress((void**)&wktl, g_wkt_l);
    cudaGetSymbolAddress((void**)&wvth, g_wvt_h); cudaGetSymbolAddress((void**)&wvtl, g_wvt_l);
    cudaGetSymbolAddress((void**)&woth, g_wot_h); cudaGetSymbolAddress((void**)&wotl, g_wot_l);
    cudaGetSymbolAddress((void**)&w1th, g_w1t_h); cudaGetSymbolAddress((void**)&w1tl, g_w1t_l);
    cudaGetSymbolAddress((void**)&w2th, g_w2t_h); cudaGetSymbolAddress((void**)&w2tl, g_w2t_l);

    cudaFuncSetAttribute(attn_kernel, cudaFuncAttributeMaxDynamicSharedMemorySize,
                         ATTN_SMEM_BYTES);
    cudaFuncSetAttribute(tc_gemm_kernel<0>, cudaFuncAttributeMaxDynamicSharedMemorySize,
                         GEMM_SMEM);
    cudaFuncSetAttribute(tc_gemm_kernel<1>, cudaFuncAttributeMaxDynamicSharedMemorySize,
                         GEMM_SMEM);
    cudaFuncSetAttribute(tc_gemm_kernel<2>, cudaFuncAttributeMaxDynamicSharedMemorySize,
                         GEMM_SMEM);

    const dim3 wblk(32, 8);
    wconv_kernel<<<dim3(D_/32,   D_/32),   wblk>>>(wq, wqth, wqtl, D_,   D_);
    wconv_kernel<<<dim3(D_/32,   D_/32),   wblk>>>(wk, wkth, wktl, D_,   D_);
    wconv_kernel<<<dim3(D_/32,   D_/32),   wblk>>>(wv, wvth, wvtl, D_,   D_);
    wconv_kernel<<<dim3(D_/32,   D_/32),   wblk>>>(wo, woth, wotl, D_,   D_);
    wconv_kernel<<<dim3(DFF_/32, D_/32),   wblk>>>(w1, w1th, w1tl, D_,   DFF_);
    wconv_kernel<<<dim3(D_/32,   DFF_/32), wblk>>>(w2, w2th, w2tl, DFF_, D_);

    // 1) pre-norm 1 -> hi/lo
    ln_hilo_kernel<<<ROWS_, 256>>>(x, a1, be1, xnh, xnl);

    const dim3 gD (D_   / NT, ROWS_ / MT);   // (8, 32)
    const dim3 gFF(DFF_ / NT, ROWS_ / MT);   // (32, 32)

    // 2) Q/K/V projections
    tc_gemm_kernel<0><<<gD, 256, GEMM_SMEM>>>(xnh, xnl, wqth, wqtl, bq, nullptr,
                                              q, nullptr, nullptr, ROWS_, D_, D_);
    tc_gemm_kernel<0><<<gD, 256, GEMM_SMEM>>>(xnh, xnl, wkth, wktl, bk, nullptr,
                                              k, nullptr, nullptr, ROWS_, D_, D_);
    tc_gemm_kernel<0><<<gD, 256, GEMM_SMEM>>>(xnh, xnl, wvth, wvtl, bv, nullptr,
                                              v, nullptr, nullptr, ROWS_, D_, D_);

    // 3) attention (fp32)
    attn_kernel<<<dim3(S_/64, H_, B_), 256, ATTN_SMEM_BYTES>>>(q, k, v, mask, ctx);

    // 4) ctx -> hi/lo, then out = x + ctx@wo + bo
    f32_to_hilo_kernel<<<(ROWS_*D_/4 + 255)/256, 256>>>(ctx, ctxh, ctxl, ROWS_*D_/4);
    tc_gemm_kernel<2><<<gD, 256, GEMM_SMEM>>>(ctxh, ctxl, woth, wotl, bo, x,
                                              out, nullptr, nullptr, ROWS_, D_, D_);

    // 5) pre-norm 2 -> hi/lo
    ln_hilo_kernel<<<ROWS_, 256>>>(out, a2, be2, xn2h, xn2l);

    // 6) FFN up + relu -> hi/lo bf16 directly
    tc_gemm_kernel<1><<<gFF, 256, GEMM_SMEM>>>(xn2h, xn2l, w1th, w1tl, b1, nullptr,
                                               nullptr, ffhh, ffhl, ROWS_, DFF_, D_);

    // 7) FFN down + residual 2 (in-place on out)
    tc_gemm_kernel<2><<<gD, 256, GEMM_SMEM>>>(ffhh, ffhl, w2th, w2tl, b2, out,
                                              out, nullptr, nullptr, ROWS_, D_, DFF_);
}

// round 11
// speedup vs baseline: 2.9706x; 1.7162x over previous
#include <cuda_runtime.h>
#include <cuda_fp16.h>
#include <math.h>
#include <stdint.h>

// ---------------------------------------------------------------------------
// Problem constants
// ---------------------------------------------------------------------------
#define B_   4
#define S_   1024
#define D_   1024
#define H_   16
#define DK_  64
#define DFF_ 4096
#define ROWS_ (B_ * S_)   // 4096

// ---------------------------------------------------------------------------
// Scratch (device globals — no allocation allowed)
// ---------------------------------------------------------------------------
__device__ float g_q  [ROWS_ * D_];
__device__ float g_k  [ROWS_ * D_];
__device__ float g_v  [ROWS_ * D_];
__device__ float g_ctx[ROWS_ * D_];

__device__ __half g_xn  [ROWS_ * D_];
__device__ __half g_xn2 [ROWS_ * D_];
__device__ __half g_ctxh[ROWS_ * D_];
__device__ __half g_ffh [(size_t)ROWS_ * DFF_];

// transposed weights [N, K] fp16
__device__ __half g_wqt[D_ * D_];
__device__ __half g_wkt[D_ * D_];
__device__ __half g_wvt[D_ * D_];
__device__ __half g_wot[D_ * D_];
__device__ __half g_w1t[(size_t)DFF_ * D_];
__device__ __half g_w2t[(size_t)D_ * DFF_];

// ---------------------------------------------------------------------------
// Helpers
// ---------------------------------------------------------------------------
__device__ __forceinline__ uint32_t smem_u32(const void* p) {
    uint32_t a;
    asm("{ .reg .u64 t; cvta.to.shared.u64 t, %1; cvt.u32.u64 %0, t; }"
        : "=r"(a) : "l"(p));
    return a;
}
__device__ __forceinline__ void cp16(uint32_t dst, const void* src) {
    asm volatile("cp.async.cg.shared.global [%0], [%1], 16;"
                 :: "r"(dst), "l"(src) : "memory");
}
#define CP_COMMIT() asm volatile("cp.async.commit_group;" ::: "memory")
#define CP_WAIT(n)  asm volatile("cp.async.wait_group %0;" :: "n"(n) : "memory")

__device__ __forceinline__ void ldmatrix_x4(uint32_t* r, uint32_t addr) {
    asm volatile("ldmatrix.sync.aligned.m8n8.x4.shared.b16 {%0,%1,%2,%3}, [%4];"
                 : "=r"(r[0]), "=r"(r[1]), "=r"(r[2]), "=r"(r[3]) : "r"(addr));
}

// fp16 warp MMA: D(16x8 f32) += A(16x16 f16, row) * B(16x8 f16, col)
__device__ __forceinline__ void mma_fp16(float* c, const uint32_t* a, const uint32_t* b) {
    asm volatile(
        "mma.sync.aligned.m16n8k16.row.col.f32.f16.f16.f32 "
        "{%0,%1,%2,%3}, {%4,%5,%6,%7}, {%8,%9}, {%0,%1,%2,%3};"
        : "+f"(c[0]), "+f"(c[1]), "+f"(c[2]), "+f"(c[3])
        : "r"(a[0]), "r"(a[1]), "r"(a[2]), "r"(a[3]), "r"(b[0]), "r"(b[1]));
}

// ---------------------------------------------------------------------------
// LayerNorm (torch semantics: ddof=1 std, eps on std, scalar alpha/beta),
// writing fp16 directly. One block per row, 256 threads.
// ---------------------------------------------------------------------------
__global__ __launch_bounds__(256)
void ln_h_kernel(const float* __restrict__ x,
                 const float* __restrict__ alpha,
                 const float* __restrict__ beta,
                 __half* __restrict__ oh)
{
    __shared__ float sbuf[8];
    const int row = blockIdx.x;
    const int tid = threadIdx.x;
    float4 xv = ((const float4*)(x + (size_t)row * D_))[tid];

    float s = xv.x + xv.y + xv.z + xv.w;
    const int lane = tid & 31, w = tid >> 5;
    #pragma unroll
    for (int o = 16; o; o >>= 1) s += __shfl_xor_sync(0xffffffffu, s, o);
    if (lane == 0) sbuf[w] = s;
    __syncthreads();
    if (w == 0) {
        float t = (lane < 8) ? sbuf[lane] : 0.f;
        #pragma unroll
        for (int o = 4; o; o >>= 1) t += __shfl_xor_sync(0xffffffffu, t, o);
        if (lane == 0) sbuf[0] = t;
    }
    __syncthreads();
    const float mean = sbuf[0] * (1.0f / (float)D_);
    __syncthreads();

    float d0 = xv.x - mean, d1 = xv.y - mean, d2 = xv.z - mean, d3 = xv.w - mean;
    float q = d0*d0 + d1*d1 + d2*d2 + d3*d3;
    #pragma unroll
    for (int o = 16; o; o >>= 1) q += __shfl_xor_sync(0xffffffffu, q, o);
    if (lane == 0) sbuf[w] = q;
    __syncthreads();
    if (w == 0) {
        float t = (lane < 8) ? sbuf[lane] : 0.f;
        #pragma unroll
        for (int o = 4; o; o >>= 1) t += __shfl_xor_sync(0xffffffffu, t, o);
        if (lane == 0) sbuf[0] = t;
    }
    __syncthreads();
    const float stdv = sqrtf(sbuf[0] * (1.0f / (float)(D_ - 1)));
    const float inv = alpha[0] / (stdv + 1e-6f);
    const float b = beta[0];

    ushort4 hv;
    hv.x = __half_as_ushort(__float2half(d0 * inv + b));
    hv.y = __half_as_ushort(__float2half(d1 * inv + b));
    hv.z = __half_as_ushort(__float2half(d2 * inv + b));
    hv.w = __half_as_ushort(__float2half(d3 * inv + b));
    ((ushort4*)(oh + (size_t)row * D_))[tid] = hv;
}

// ---------------------------------------------------------------------------
// fp32 -> fp16 elementwise converter (attention context output)
// ---------------------------------------------------------------------------
__global__ __launch_bounds__(256)
void f32_to_h_kernel(const float* __restrict__ in, __half* __restrict__ oh, int n4)
{
    int i = blockIdx.x * blockDim.x + threadIdx.x;
    if (i >= n4) return;
    float4 v = ((const float4*)in)[i];
    ushort4 hv;
    hv.x = __half_as_ushort(__float2half(v.x));
    hv.y = __half_as_ushort(__float2half(v.y));
    hv.z = __half_as_ushort(__float2half(v.z));
    hv.w = __half_as_ushort(__float2half(v.w));
    ((ushort4*)oh)[i] = hv;
}

// ---------------------------------------------------------------------------
// Weight convert + transpose: W[K,N] fp32 -> T[N,K] fp16.
// ---------------------------------------------------------------------------
__global__ __launch_bounds__(256)
void wconv_kernel(const float* __restrict__ W, __half* __restrict__ T, int K, int N)
{
    __shared__ float s[32][33];
    const int kb = blockIdx.y * 32, nb = blockIdx.x * 32;
    const int tx = threadIdx.x, ty = threadIdx.y;
    #pragma unroll
    for (int i = 0; i < 4; i++)
        s[ty + i*8][tx] = W[(size_t)(kb + ty + i*8) * N + nb + tx];
    __syncthreads();
    #pragma unroll
    for (int i = 0; i < 4; i++) {
        int n = nb + ty + i*8, k = kb + tx;
        T[(size_t)n * K + k] = __float2half(s[tx][ty + i*8]);
    }
}

// ---------------------------------------------------------------------------
// fp16 single-pass tensor-core GEMM via mma.sync + ldmatrix:
//   C[M,N] = epi(A[M,K] @ W[K,N] + bias)
// A fp16 [M,K]; W transposed fp16 [N,K]. fp32 accumulate.
// 128x128 tile, KT=64, 3-stage cp.async pipeline, 8 warps (2x4),
// warp tile 64x32 (4x4 m16n8k16 frags). SMEM row pitch 72 fp16 (conflict-free).
//   EPI 0: fp32 = acc + bias
//   EPI 1: fp16 = relu(acc + bias)
//   EPI 2: fp32 = acc + bias + res   (res may alias C)
// ---------------------------------------------------------------------------
#define MT 128
#define NT 128
#define KT 64
#define PITCH 72                        // fp16 per smem row (64 data + 8 pad)
#define TILE_E (128 * PITCH)            // 9216 fp16 per tile
#define STAGE_E (2 * TILE_E)            // A + B
#define NSTAGE 3
#define GEMM_SMEM (NSTAGE * STAGE_E * 2)  // 110592 bytes

__device__ __forceinline__ void issue_stage(
        uint32_t sdst,
        const __half* __restrict__ A, const __half* __restrict__ Bm,
        int K, int k0, int bm, int bn, int tid)
{
    #pragma unroll
    for (int i = 0; i < 8; i++) {
        const int gid  = i * 256 + tid;
        const int tile = gid >> 10;       // 0: A, 1: B
        const int rem  = gid & 1023;
        const int row  = rem >> 3;
        const int ch   = rem & 7;         // 16B chunk within 128B row
        const __half* base = tile ? Bm : A;
        const int grow = (tile ? bn : bm) + row;
        const __half* src = base + (size_t)grow * K + k0 + ch * 8;
        const uint32_t dst = sdst +
            (uint32_t)(tile * TILE_E + row * PITCH + ch * 8) * 2;
        cp16(dst, src);
    }
}

template<int EPI>
__global__ __launch_bounds__(256, 2)
void tc_gemm_kernel(const __half* __restrict__ A,
                    const __half* __restrict__ Bm,
                    const float* __restrict__ bias,
                    const float* __restrict__ res,
                    float* __restrict__ C,
                    __half* __restrict__ Ch,
                    int M, int N, int K)
{
    extern __shared__ char smraw[];
    const uint32_t smb = smem_u32(smraw);

    const int tid  = threadIdx.x;
    const int wid  = tid >> 5, lane = tid & 31;
    const int gidq = lane >> 2, tig = lane & 3;
    const int wm   = wid >> 2, wn = wid & 3;      // 2 x 4 warp grid
    const int bm   = blockIdx.y * MT, bn = blockIdx.x * NT;

    // ldmatrix lane addressing (canonical x4 pattern)
    const int lrow = lane & 15;
    const int lcol = (lane >> 4) * 8;

    float acc[4][4][4];
    #pragma unroll
    for (int i = 0; i < 4; i++)
        #pragma unroll
        for (int j = 0; j < 4; j++)
            #pragma unroll
            for (int r = 0; r < 4; r++) acc[i][j][r] = 0.f;

    const int NK = K / KT;

    issue_stage(smb, A, Bm, K, 0, bm, bn, tid);
    CP_COMMIT();
    issue_stage(smb + STAGE_E * 2, A, Bm, K, KT, bm, bn, tid);
    CP_COMMIT();

    for (int kt = 0; kt < NK; ++kt) {
        __syncthreads();   // compute of the stage about to be refilled is done
        if (kt + 2 < NK) {
            issue_stage(smb + (uint32_t)((kt + 2) % 3) * STAGE_E * 2,
                        A, Bm, K, (kt + 2) * KT, bm, bn, tid);
            CP_COMMIT();
            CP_WAIT(2);
        } else if (kt + 1 < NK) {
            CP_WAIT(1);
        } else {
            CP_WAIT(0);
        }
        __syncthreads();

        const uint32_t sA = smb + (uint32_t)(kt % 3) * STAGE_E * 2;
        const uint32_t sB = sA + TILE_E * 2;
        const uint32_t aBase = sA + (uint32_t)((wm * 64 + lrow) * PITCH + lcol) * 2;
        const uint32_t bBase = sB + (uint32_t)((wn * 32 + lrow) * PITCH + lcol) * 2;

        #pragma unroll
        for (int st = 0; st < 4; st++) {
            const uint32_t kb = (uint32_t)(st * 16) * 2;
            uint32_t a[4][4], bf[4][2];
            #pragma unroll
            for (int mf = 0; mf < 4; mf++)
                ldmatrix_x4(a[mf], aBase + (uint32_t)(mf * 16 * PITCH) * 2 + kb);
            #pragma unroll
            for (int pr = 0; pr < 2; pr++) {
                uint32_t t[4];
                ldmatrix_x4(t, bBase + (uint32_t)(pr * 16 * PITCH) * 2 + kb);
                bf[2*pr][0] = t[0]; bf[2*pr+1][0] = t[1];
                bf[2*pr][1] = t[2]; bf[2*pr+1][1] = t[3];
            }
            #pragma unroll
            for (int mf = 0; mf < 4; mf++)
                #pragma unroll
                for (int nf = 0; nf < 4; nf++)
                    mma_fp16(acc[mf][nf], a[mf], bf[nf]);
        }
    }

    // ---- epilogue ----
    #pragma unroll
    for (int mf = 0; mf < 4; mf++) {
        #pragma unroll
        for (int nf = 0; nf < 4; nf++) {
            const int r = bm + wm * 64 + mf * 16 + gidq;
            const int c = bn + wn * 32 + nf * 8 + tig * 2;
            const float b0 = __ldg(&bias[c]), b1 = __ldg(&bias[c + 1]);
            float v00 = acc[mf][nf][0] + b0, v01 = acc[mf][nf][1] + b1;
            float v10 = acc[mf][nf][2] + b0, v11 = acc[mf][nf][3] + b1;
            if (EPI == 1) {
                v00 = fmaxf(v00, 0.f); v01 = fmaxf(v01, 0.f);
                v10 = fmaxf(v10, 0.f); v11 = fmaxf(v11, 0.f);
                uint32_t w0 = (uint32_t)__half_as_ushort(__float2half(v00)) |
                              ((uint32_t)__half_as_ushort(__float2half(v01)) << 16);
                uint32_t w1 = (uint32_t)__half_as_ushort(__float2half(v10)) |
                              ((uint32_t)__half_as_ushort(__float2half(v11)) << 16);
                *(uint32_t*)(Ch + (size_t)r * N + c) = w0;
                *(uint32_t*)(Ch + (size_t)(r + 8) * N + c) = w1;
            } else {
                if (EPI == 2) {
                    float2 r0 = *(const float2*)(res + (size_t)r * N + c);
                    float2 r1 = *(const float2*)(res + (size_t)(r + 8) * N + c);
                    v00 += r0.x; v01 += r0.y; v10 += r1.x; v11 += r1.y;
                }
                *(float2*)(C + (size_t)r * N + c) = make_float2(v00, v01);
                *(float2*)(C + (size_t)(r + 8) * N + c) = make_float2(v10, v11);
            }
        }
    }
}

// ---------------------------------------------------------------------------
// Flash-style attention (fp32), vectorized LDS.
// Grid: (q_tiles=16, H=16, B=4). 256 threads.
// SMEM layout [row][dk] pitch 68 (conflict-free float4).
// ---------------------------------------------------------------------------
#define APITCH 68
#define ATTN_SMEM_BYTES ((3 * 64 * APITCH + 256) * 4)   // 53248

__global__ __launch_bounds__(256)
void attn_kernel(const float* __restrict__ q, const float* __restrict__ k,
                 const float* __restrict__ v, const int* __restrict__ mask,
                 float* __restrict__ ctx)
{
    extern __shared__ char smraw[];
    float* smf = (float*)smraw;
    float* Qs  = smf;                       // [64][APITCH]  Q[r][dk]
    float* KP  = smf + 64 * APITCH;         // K[key][dk], reused as P[key][r]
    float* Vs  = smf + 2 * 64 * APITCH;     // V[key][dk]
    float* red = smf + 3 * 64 * APITCH;     // [4][64]

    const int tid = threadIdx.x;
    const int r   = tid & 63;
    const int cg  = tid >> 6;
    const int c0  = cg * 16;
    const int qt  = blockIdx.x, h = blockIdx.y, b = blockIdx.z;

    {
        const float* qp = q + ((size_t)(b * S_ + qt * 64 + r)) * D_ + h * 64 + c0;
        #pragma unroll
        for (int j = 0; j < 16; j += 4)
            *(float4*)&Qs[r * APITCH + c0 + j] = *(const float4*)(qp + j);
    }

    float O[16];
    #pragma unroll
    for (int j = 0; j < 16; j++) O[j] = 0.f;
    float m = -1e30f, l = 0.f;
    const int* mrow = mask + b * S_;

    for (int kt = 0; kt < 16; kt++) {
        __syncthreads();   // previous tile consumers done; Q visible on iter 0
        {
            const float* kp = k + ((size_t)(b * S_ + kt * 64 + r)) * D_ + h * 64 + c0;
            const float* vp = v + ((size_t)(b * S_ + kt * 64 + r)) * D_ + h * 64 + c0;
            #pragma unroll
            for (int j = 0; j < 16; j += 4) {
                *(float4*)&KP[r * APITCH + c0 + j] = *(const float4*)(kp + j);
                *(float4*)&Vs[r * APITCH + c0 + j] = *(const float4*)(vp + j);
            }
        }
        __syncthreads();

        // scores: s[j] = sum_dk Q[r][dk] * K[c0+j][dk]   (K loads broadcast)
        float s[16];
        #pragma unroll
        for (int j = 0; j < 16; j++) s[j] = 0.f;
        #pragma unroll 4
        for (int kk = 0; kk < 64; kk += 4) {
            float4 qv = *(const float4*)&Qs[r * APITCH + kk];
            #pragma unroll
            for (int j = 0; j < 16; j++) {
                float4 kv = *(const float4*)&KP[(c0 + j) * APITCH + kk];
                s[j] = fmaf(qv.x, kv.x, s[j]);
                s[j] = fmaf(qv.y, kv.y, s[j]);
                s[j] = fmaf(qv.z, kv.z, s[j]);
                s[j] = fmaf(qv.w, kv.w, s[j]);
            }
        }

        float pm = -1e30f;
        #pragma unroll
        for (int j = 0; j < 16; j++) {
            s[j] *= 0.125f;                          // 1/sqrt(64)
            if (mrow[kt * 64 + c0 + j] == 0) s[j] = -1e9f;
            pm = fmaxf(pm, s[j]);
        }
        red[cg * 64 + r] = pm;
        __syncthreads();   // also orders: K reads done before P overwrites KP

        float mn = fmaxf(fmaxf(red[r], red[64 + r]), fmaxf(red[128 + r], red[192 + r]));
        mn = fmaxf(mn, m);
        const float alpha = expf(m - mn);

        float psum = 0.f;
        #pragma unroll
        for (int j = 0; j < 16; j++) {
            float p = expf(s[j] - mn);
            psum += p;
            KP[(c0 + j) * APITCH + r] = p;           // P[key][qrow]
        }
        __syncthreads();   // red max reads done; P writes visible
        red[cg * 64 + r] = psum;
        __syncthreads();
        const float rs = red[r] + red[64 + r] + red[128 + r] + red[192 + r];

        l = l * alpha + rs;
        #pragma unroll
        for (int j = 0; j < 16; j++) O[j] *= alpha;

        // ctx: O[r][c0+j] += sum_c P[r][c] * V[c][c0+j]  (V loads broadcast)
        #pragma unroll 2
        for (int cc = 0; cc < 64; cc++) {
            const float p = KP[cc * APITCH + r];
            const float* vrow = &Vs[cc * APITCH + c0];
            float4 v0 = *(const float4*)(vrow);
            float4 v1 = *(const float4*)(vrow + 4);
            float4 v2 = *(const float4*)(vrow + 8);
            float4 v3 = *(const float4*)(vrow + 12);
            O[0]  = fmaf(p, v0.x, O[0]);  O[1]  = fmaf(p, v0.y, O[1]);
            O[2]  = fmaf(p, v0.z, O[2]);  O[3]  = fmaf(p, v0.w, O[3]);
            O[4]  = fmaf(p, v1.x, O[4]);  O[5]  = fmaf(p, v1.y, O[5]);
            O[6]  = fmaf(p, v1.z, O[6]);  O[7]  = fmaf(p, v1.w, O[7]);
            O[8]  = fmaf(p, v2.x, O[8]);  O[9]  = fmaf(p, v2.y, O[9]);
            O[10] = fmaf(p, v2.z, O[10]); O[11] = fmaf(p, v2.w, O[11]);
            O[12] = fmaf(p, v3.x, O[12]); O[13] = fmaf(p, v3.y, O[13]);
            O[14] = fmaf(p, v3.z, O[14]); O[15] = fmaf(p, v3.w, O[15]);
        }
        m = mn;
    }

    const float inv = 1.f / l;
    float* op = ctx + ((size_t)(b * S_ + qt * 64 + r)) * D_ + h * 64 + c0;
    #pragma unroll
    for (int j = 0; j < 16; j++) op[j] = O[j] * inv;
}

// ---------------------------------------------------------------------------
// Launch
// ---------------------------------------------------------------------------
extern "C" void kernel_launch(void* const* d_in, const int* in_sizes, int n_in,
                              void* d_out, int out_size)
{
    const float* x    = (const float*)d_in[0];
    const int*   mask = (const int*)  d_in[1];
    const float* wq   = (const float*)d_in[2];
    const float* bq   = (const float*)d_in[3];
    const float* wk   = (const float*)d_in[4];
    const float* bk   = (const float*)d_in[5];
    const float* wv   = (const float*)d_in[6];
    const float* bv   = (const float*)d_in[7];
    const float* wo   = (const float*)d_in[8];
    const float* bo   = (const float*)d_in[9];
    const float* w1   = (const float*)d_in[10];
    const float* b1   = (const float*)d_in[11];
    const float* w2   = (const float*)d_in[12];
    const float* b2   = (const float*)d_in[13];
    const float* a1   = (const float*)d_in[14];
    const float* be1  = (const float*)d_in[15];
    const float* a2   = (const float*)d_in[16];
    const float* be2  = (const float*)d_in[17];
    float* out = (float*)d_out;

    float *q, *k, *v, *ctx;
    __half *xn, *xn2, *ctxh, *ffh;
    __half *wqt, *wkt, *wvt, *wot, *w1t, *w2t;
    cudaGetSymbolAddress((void**)&q,    g_q);
    cudaGetSymbolAddress((void**)&k,    g_k);
    cudaGetSymbolAddress((void**)&v,    g_v);
    cudaGetSymbolAddress((void**)&ctx,  g_ctx);
    cudaGetSymbolAddress((void**)&xn,   g_xn);
    cudaGetSymbolAddress((void**)&xn2,  g_xn2);
    cudaGetSymbolAddress((void**)&ctxh, g_ctxh);
    cudaGetSymbolAddress((void**)&ffh,  g_ffh);
    cudaGetSymbolAddress((void**)&wqt,  g_wqt);
    cudaGetSymbolAddress((void**)&wkt,  g_wkt);
    cudaGetSymbolAddress((void**)&wvt,  g_wvt);
    cudaGetSymbolAddress((void**)&wot,  g_wot);
    cudaGetSymbolAddress((void**)&w1t,  g_w1t);
    cudaGetSymbolAddress((void**)&w2t,  g_w2t);

    cudaFuncSetAttribute(attn_kernel, cudaFuncAttributeMaxDynamicSharedMemorySize,
                         ATTN_SMEM_BYTES);
    cudaFuncSetAttribute(tc_gemm_kernel<0>, cudaFuncAttributeMaxDynamicSharedMemorySize,
                         GEMM_SMEM);
    cudaFuncSetAttribute(tc_gemm_kernel<1>, cudaFuncAttributeMaxDynamicSharedMemorySize,
                         GEMM_SMEM);
    cudaFuncSetAttribute(tc_gemm_kernel<2>, cudaFuncAttributeMaxDynamicSharedMemorySize,
                         GEMM_SMEM);

    const dim3 wblk(32, 8);
    wconv_kernel<<<dim3(D_/32,   D_/32),   wblk>>>(wq, wqt, D_,   D_);
    wconv_kernel<<<dim3(D_/32,   D_/32),   wblk>>>(wk, wkt, D_,   D_);
    wconv_kernel<<<dim3(D_/32,   D_/32),   wblk>>>(wv, wvt, D_,   D_);
    wconv_kernel<<<dim3(D_/32,   D_/32),   wblk>>>(wo, wot, D_,   D_);
    wconv_kernel<<<dim3(DFF_/32, D_/32),   wblk>>>(w1, w1t, D_,   DFF_);
    wconv_kernel<<<dim3(D_/32,   DFF_/32), wblk>>>(w2, w2t, DFF_, D_);

    // 1) pre-norm 1 -> fp16
    ln_h_kernel<<<ROWS_, 256>>>(x, a1, be1, xn);

    const dim3 gD (D_   / NT, ROWS_ / MT);   // (8, 32)
    const dim3 gFF(DFF_ / NT, ROWS_ / MT);   // (32, 32)

    // 2) Q/K/V projections
    tc_gemm_kernel<0><<<gD, 256, GEMM_SMEM>>>(xn, wqt, bq, nullptr, q, nullptr,
                                              ROWS_, D_, D_);
    tc_gemm_kernel<0><<<gD, 256, GEMM_SMEM>>>(xn, wkt, bk, nullptr, k, nullptr,
                                              ROWS_, D_, D_);
    tc_gemm_kernel<0><<<gD, 256, GEMM_SMEM>>>(xn, wvt, bv, nullptr, v, nullptr,
                                              ROWS_, D_, D_);

    // 3) attention (fp32)
    attn_kernel<<<dim3(S_/64, H_, B_), 256, ATTN_SMEM_BYTES>>>(q, k, v, mask, ctx);

    // 4) ctx -> fp16, then out = x + ctx@wo + bo
    f32_to_h_kernel<<<(ROWS_*D_/4 + 255)/256, 256>>>(ctx, ctxh, ROWS_*D_/4);
    tc_gemm_kernel<2><<<gD, 256, GEMM_SMEM>>>(ctxh, wot, bo, x, out, nullptr,
                                              ROWS_, D_, D_);

    // 5) pre-norm 2 -> fp16
    ln_h_kernel<<<ROWS_, 256>>>(out, a2, be2, xn2);

    // 6) FFN up + relu -> fp16
    tc_gemm_kernel<1><<<gFF, 256, GEMM_SMEM>>>(xn2, w1t, b1, nullptr, nullptr, ffh,
                                               ROWS_, DFF_, D_);

    // 7) FFN down + residual 2 (in-place on out)
    tc_gemm_kernel<2><<<gD, 256, GEMM_SMEM>>>(ffh, w2t, b2, out, out, nullptr,
                                              ROWS_, D_, DFF_);
}

// round 17
// speedup vs baseline: 6.8339x; 2.3005x over previous
#include <cuda_runtime.h>
#include <cuda_fp16.h>
#include <math.h>
#include <stdint.h>

// ---------------------------------------------------------------------------
// Problem constants
// ---------------------------------------------------------------------------
#define B_   4
#define S_   1024
#define D_   1024
#define H_   16
#define DK_  64
#define DFF_ 4096
#define ROWS_ (B_ * S_)   // 4096

// ---------------------------------------------------------------------------
// Scratch (device globals — no allocation allowed)
// ---------------------------------------------------------------------------
__device__ __half g_qh  [ROWS_ * D_];
__device__ __half g_kh  [ROWS_ * D_];
__device__ __half g_vh  [ROWS_ * D_];
__device__ __half g_ctxh[ROWS_ * D_];
__device__ __half g_xn  [ROWS_ * D_];
__device__ __half g_xn2 [ROWS_ * D_];
__device__ __half g_ffh [(size_t)ROWS_ * DFF_];

// transposed weights [N, K] fp16
__device__ __half g_wqt[D_ * D_];
__device__ __half g_wkt[D_ * D_];
__device__ __half g_wvt[D_ * D_];
__device__ __half g_wot[D_ * D_];
__device__ __half g_w1t[(size_t)DFF_ * D_];
__device__ __half g_w2t[(size_t)D_ * DFF_];

// ---------------------------------------------------------------------------
// Helpers
// ---------------------------------------------------------------------------
__device__ __forceinline__ uint32_t smem_u32(const void* p) {
    uint32_t a;
    asm("{ .reg .u64 t; cvta.to.shared.u64 t, %1; cvt.u32.u64 %0, t; }"
        : "=r"(a) : "l"(p));
    return a;
}
__device__ __forceinline__ void cp16(uint32_t dst, const void* src) {
    asm volatile("cp.async.cg.shared.global [%0], [%1], 16;"
                 :: "r"(dst), "l"(src) : "memory");
}
#define CP_COMMIT() asm volatile("cp.async.commit_group;" ::: "memory")
#define CP_WAIT(n)  asm volatile("cp.async.wait_group %0;" :: "n"(n) : "memory")

__device__ __forceinline__ void ldmatrix_x4(uint32_t* r, uint32_t addr) {
    asm volatile("ldmatrix.sync.aligned.m8n8.x4.shared.b16 {%0,%1,%2,%3}, [%4];"
                 : "=r"(r[0]), "=r"(r[1]), "=r"(r[2]), "=r"(r[3]) : "r"(addr));
}
__device__ __forceinline__ void ldmatrix_x4_trans(uint32_t* r, uint32_t addr) {
    asm volatile("ldmatrix.sync.aligned.m8n8.x4.trans.shared.b16 {%0,%1,%2,%3}, [%4];"
                 : "=r"(r[0]), "=r"(r[1]), "=r"(r[2]), "=r"(r[3]) : "r"(addr));
}

// fp16 warp MMA: D(16x8 f32) += A(16x16 f16, row) * B(16x8 f16, col)
__device__ __forceinline__ void mma_fp16(float* c, const uint32_t* a, const uint32_t* b) {
    asm volatile(
        "mma.sync.aligned.m16n8k16.row.col.f32.f16.f16.f32 "
        "{%0,%1,%2,%3}, {%4,%5,%6,%7}, {%8,%9}, {%0,%1,%2,%3};"
        : "+f"(c[0]), "+f"(c[1]), "+f"(c[2]), "+f"(c[3])
        : "r"(a[0]), "r"(a[1]), "r"(a[2]), "r"(a[3]), "r"(b[0]), "r"(b[1]));
}

__device__ __forceinline__ uint32_t pack_h2(float a, float b) {
    __half2 h = __floats2half2_rn(a, b);
    return *(uint32_t*)&h;
}

// ---------------------------------------------------------------------------
// LayerNorm (torch semantics: ddof=1 std, eps on std, scalar alpha/beta),
// writing fp16 directly. One block per row, 256 threads.
// ---------------------------------------------------------------------------
__global__ __launch_bounds__(256)
void ln_h_kernel(const float* __restrict__ x,
                 const float* __restrict__ alpha,
                 const float* __restrict__ beta,
                 __half* __restrict__ oh)
{
    __shared__ float sbuf[8];
    const int row = blockIdx.x;
    const int tid = threadIdx.x;
    float4 xv = ((const float4*)(x + (size_t)row * D_))[tid];

    float s = xv.x + xv.y + xv.z + xv.w;
    const int lane = tid & 31, w = tid >> 5;
    #pragma unroll
    for (int o = 16; o; o >>= 1) s += __shfl_xor_sync(0xffffffffu, s, o);
    if (lane == 0) sbuf[w] = s;
    __syncthreads();
    if (w == 0) {
        float t = (lane < 8) ? sbuf[lane] : 0.f;
        #pragma unroll
        for (int o = 4; o; o >>= 1) t += __shfl_xor_sync(0xffffffffu, t, o);
        if (lane == 0) sbuf[0] = t;
    }
    __syncthreads();
    const float mean = sbuf[0] * (1.0f / (float)D_);
    __syncthreads();

    float d0 = xv.x - mean, d1 = xv.y - mean, d2 = xv.z - mean, d3 = xv.w - mean;
    float q = d0*d0 + d1*d1 + d2*d2 + d3*d3;
    #pragma unroll
    for (int o = 16; o; o >>= 1) q += __shfl_xor_sync(0xffffffffu, q, o);
    if (lane == 0) sbuf[w] = q;
    __syncthreads();
    if (w == 0) {
        float t = (lane < 8) ? sbuf[lane] : 0.f;
        #pragma unroll
        for (int o = 4; o; o >>= 1) t += __shfl_xor_sync(0xffffffffu, t, o);
        if (lane == 0) sbuf[0] = t;
    }
    __syncthreads();
    const float stdv = sqrtf(sbuf[0] * (1.0f / (float)(D_ - 1)));
    const float inv = alpha[0] / (stdv + 1e-6f);
    const float b = beta[0];

    ushort4 hv;
    hv.x = __half_as_ushort(__float2half(d0 * inv + b));
    hv.y = __half_as_ushort(__float2half(d1 * inv + b));
    hv.z = __half_as_ushort(__float2half(d2 * inv + b));
    hv.w = __half_as_ushort(__float2half(d3 * inv + b));
    ((ushort4*)(oh + (size_t)row * D_))[tid] = hv;
}

// ---------------------------------------------------------------------------
// Weight convert + transpose: W[K,N] fp32 -> T[N,K] fp16.
// ---------------------------------------------------------------------------
__global__ __launch_bounds__(256)
void wconv_kernel(const float* __restrict__ W, __half* __restrict__ T, int K, int N)
{
    __shared__ float s[32][33];
    const int kb = blockIdx.y * 32, nb = blockIdx.x * 32;
    const int tx = threadIdx.x, ty = threadIdx.y;
    #pragma unroll
    for (int i = 0; i < 4; i++)
        s[ty + i*8][tx] = W[(size_t)(kb + ty + i*8) * N + nb + tx];
    __syncthreads();
    #pragma unroll
    for (int i = 0; i < 4; i++) {
        int n = nb + ty + i*8, k = kb + tx;
        T[(size_t)n * K + k] = __float2half(s[tx][ty + i*8]);
    }
}

// ---------------------------------------------------------------------------
// fp16 single-pass tensor-core GEMM via mma.sync + ldmatrix:
//   C[M,N] = epi(A[M,K] @ W[K,N] + bias)
// A fp16 [M,K]; W transposed fp16 [N,K]. fp32 accumulate.
// 128x128 tile, KT=64, 3-stage cp.async pipeline, 8 warps (2x4),
// warp tile 64x32 (4x4 m16n8k16 frags). SMEM row pitch 72 fp16.
//   EPI 1: fp16 = relu(acc + bias)
//   EPI 2: fp32 = acc + bias + res   (res may alias C)
//   EPI 3: fp16 = acc + bias
// ---------------------------------------------------------------------------
#define MT 128
#define NT 128
#define KT 64
#define PITCH 72
#define TILE_E (128 * PITCH)
#define STAGE_E (2 * TILE_E)
#define NSTAGE 3
#define GEMM_SMEM (NSTAGE * STAGE_E * 2)  // 110592 bytes

__device__ __forceinline__ void issue_stage(
        uint32_t sdst,
        const __half* __restrict__ A, const __half* __restrict__ Bm,
        int K, int k0, int bm, int bn, int tid)
{
    #pragma unroll
    for (int i = 0; i < 8; i++) {
        const int gid  = i * 256 + tid;
        const int tile = gid >> 10;       // 0: A, 1: B
        const int rem  = gid & 1023;
        const int row  = rem >> 3;
        const int ch   = rem & 7;
        const __half* base = tile ? Bm : A;
        const int grow = (tile ? bn : bm) + row;
        const __half* src = base + (size_t)grow * K + k0 + ch * 8;
        const uint32_t dst = sdst +
            (uint32_t)(tile * TILE_E + row * PITCH + ch * 8) * 2;
        cp16(dst, src);
    }
}

template<int EPI>
__global__ __launch_bounds__(256, 2)
void tc_gemm_kernel(const __half* __restrict__ A,
                    const __half* __restrict__ Bm,
                    const float* __restrict__ bias,
                    const float* __restrict__ res,
                    float* __restrict__ C,
                    __half* __restrict__ Ch,
                    int M, int N, int K)
{
    extern __shared__ char smraw[];
    const uint32_t smb = smem_u32(smraw);

    const int tid  = threadIdx.x;
    const int wid  = tid >> 5, lane = tid & 31;
    const int gidq = lane >> 2, tig = lane & 3;
    const int wm   = wid >> 2, wn = wid & 3;
    const int bm   = blockIdx.y * MT, bn = blockIdx.x * NT;
    const int lrow = lane & 15;
    const int lcol = (lane >> 4) * 8;

    float acc[4][4][4];
    #pragma unroll
    for (int i = 0; i < 4; i++)
        #pragma unroll
        for (int j = 0; j < 4; j++)
            #pragma unroll
            for (int r = 0; r < 4; r++) acc[i][j][r] = 0.f;

    const int NK = K / KT;

    issue_stage(smb, A, Bm, K, 0, bm, bn, tid);
    CP_COMMIT();
    issue_stage(smb + STAGE_E * 2, A, Bm, K, KT, bm, bn, tid);
    CP_COMMIT();

    for (int kt = 0; kt < NK; ++kt) {
        __syncthreads();
        if (kt + 2 < NK) {
            issue_stage(smb + (uint32_t)((kt + 2) % 3) * STAGE_E * 2,
                        A, Bm, K, (kt + 2) * KT, bm, bn, tid);
            CP_COMMIT();
            CP_WAIT(2);
        } else if (kt + 1 < NK) {
            CP_WAIT(1);
        } else {
            CP_WAIT(0);
        }
        __syncthreads();

        const uint32_t sA = smb + (uint32_t)(kt % 3) * STAGE_E * 2;
        const uint32_t sB = sA + TILE_E * 2;
        const uint32_t aBase = sA + (uint32_t)((wm * 64 + lrow) * PITCH + lcol) * 2;
        const uint32_t bBase = sB + (uint32_t)((wn * 32 + lrow) * PITCH + lcol) * 2;

        #pragma unroll
        for (int st = 0; st < 4; st++) {
            const uint32_t kb = (uint32_t)(st * 16) * 2;
            uint32_t a[4][4], bf[4][2];
            #pragma unroll
            for (int mf = 0; mf < 4; mf++)
                ldmatrix_x4(a[mf], aBase + (uint32_t)(mf * 16 * PITCH) * 2 + kb);
            #pragma unroll
            for (int pr = 0; pr < 2; pr++) {
                uint32_t t[4];
                ldmatrix_x4(t, bBase + (uint32_t)(pr * 16 * PITCH) * 2 + kb);
                bf[2*pr][0] = t[0]; bf[2*pr+1][0] = t[1];
                bf[2*pr][1] = t[2]; bf[2*pr+1][1] = t[3];
            }
            #pragma unroll
            for (int mf = 0; mf < 4; mf++)
                #pragma unroll
                for (int nf = 0; nf < 4; nf++)
                    mma_fp16(acc[mf][nf], a[mf], bf[nf]);
        }
    }

    // ---- epilogue ----
    #pragma unroll
    for (int mf = 0; mf < 4; mf++) {
        #pragma unroll
        for (int nf = 0; nf < 4; nf++) {
            const int r = bm + wm * 64 + mf * 16 + gidq;
            const int c = bn + wn * 32 + nf * 8 + tig * 2;
            const float b0 = __ldg(&bias[c]), b1 = __ldg(&bias[c + 1]);
            float v00 = acc[mf][nf][0] + b0, v01 = acc[mf][nf][1] + b1;
            float v10 = acc[mf][nf][2] + b0, v11 = acc[mf][nf][3] + b1;
            if (EPI == 1 || EPI == 3) {
                if (EPI == 1) {
                    v00 = fmaxf(v00, 0.f); v01 = fmaxf(v01, 0.f);
                    v10 = fmaxf(v10, 0.f); v11 = fmaxf(v11, 0.f);
                }
                *(uint32_t*)(Ch + (size_t)r * N + c) = pack_h2(v00, v01);
                *(uint32_t*)(Ch + (size_t)(r + 8) * N + c) = pack_h2(v10, v11);
            } else {
                if (EPI == 2) {
                    float2 r0 = *(const float2*)(res + (size_t)r * N + c);
                    float2 r1 = *(const float2*)(res + (size_t)(r + 8) * N + c);
                    v00 += r0.x; v01 += r0.y; v10 += r1.x; v11 += r1.y;
                }
                *(float2*)(C + (size_t)r * N + c) = make_float2(v00, v01);
                *(float2*)(C + (size_t)(r + 8) * N + c) = make_float2(v10, v11);
            }
        }
    }
}

// ---------------------------------------------------------------------------
// Tensor-core flash attention (fp16 in, fp32 softmax/accum, fp16 out).
// Grid: (qtiles=16, H=16, B=4), 128 threads (4 warps, 16 q-rows each).
// K/V 64-key tiles double-buffered via cp.async.
// ---------------------------------------------------------------------------
#define AP 72                               // fp16 pitch
#define AT_TILE_B (64 * AP * 2)             // 9216 bytes per 64x64 tile
#define ATTN_SMEM (AT_TILE_B * 5 + S_ * 4)  // Q + 2K + 2V + mask = 50176

// Full 64x64 fp16 tile = 64 rows x 8 chunks of 16B = 512 cp16 per tile.
__device__ __forceinline__ void attn_issue_kv(
        uint32_t kDst, uint32_t vDst,
        const __half* __restrict__ kh, const __half* __restrict__ vh,
        int b, int h, int kt, int tid)
{
    #pragma unroll
    for (int i = 0; i < 4; i++) {
        const int idx = i * 128 + tid;       // 0..511
        const int r = idx >> 3, ch = idx & 7;
        const size_t g = ((size_t)(b * S_ + kt * 64 + r)) * D_ + h * 64 + ch * 8;
        const uint32_t so = (uint32_t)(r * AP + ch * 8) * 2;
        cp16(kDst + so, kh + g);
        cp16(vDst + so, vh + g);
    }
}

__global__ __launch_bounds__(128)
void attn_tc_kernel(const __half* __restrict__ qh, const __half* __restrict__ kh,
                    const __half* __restrict__ vh, const int* __restrict__ mask,
                    __half* __restrict__ ctxh)
{
    extern __shared__ char smraw[];
    const uint32_t smb = smem_u32(smraw);
    const uint32_t qOff = 0;
    const uint32_t kOff = AT_TILE_B;
    const uint32_t vOff = AT_TILE_B * 3;
    int* msk = (int*)(smraw + AT_TILE_B * 5);

    const int tid = threadIdx.x, wid = tid >> 5, lane = tid & 31;
    const int gidq = lane >> 2, tig = lane & 3;
    const int qt = blockIdx.x, h = blockIdx.y, b = blockIdx.z;

    // mask -> smem (plain loads)
    for (int i = tid; i < S_ / 4; i += 128)
        ((int4*)msk)[i] = ((const int4*)(mask + b * S_))[i];

    // Q tile (64 rows x 64 cols fp16 = 512 chunks) via cp.async
    #pragma unroll
    for (int i = 0; i < 4; i++) {
        const int idx = i * 128 + tid;
        const int r = idx >> 3, ch = idx & 7;
        const __half* src = qh + ((size_t)(b * S_ + qt * 64 + r)) * D_ + h * 64 + ch * 8;
        cp16(smb + qOff + (uint32_t)(r * AP + ch * 8) * 2, src);
    }
    attn_issue_kv(smb + kOff, smb + vOff, kh, vh, b, h, 0, tid);
    CP_COMMIT();

    float sc[8][4], O[8][4];
    #pragma unroll
    for (int i = 0; i < 8; i++)
        #pragma unroll
        for (int r = 0; r < 4; r++) O[i][r] = 0.f;
    float mr0 = -1e30f, mr1 = -1e30f, lr0 = 0.f, lr1 = 0.f;

    uint32_t aq[4][4];
    const uint32_t lmOff = (uint32_t)((lane & 15) * AP + (lane >> 4) * 8) * 2;
    const uint32_t qBase = smb + qOff + (uint32_t)(wid * 16 * AP) * 2 + lmOff;

    for (int kt = 0; kt < 16; ++kt) {
        const int s = kt & 1;
        if (kt + 1 < 16) {
            attn_issue_kv(smb + kOff + (uint32_t)(s ^ 1) * AT_TILE_B,
                          smb + vOff + (uint32_t)(s ^ 1) * AT_TILE_B,
                          kh, vh, b, h, kt + 1, tid);
            CP_COMMIT();
            CP_WAIT(1);
        } else {
            CP_WAIT(0);
        }
        __syncthreads();

        if (kt == 0) {
            #pragma unroll
            for (int ks = 0; ks < 4; ks++)
                ldmatrix_x4(aq[ks], qBase + (uint32_t)(ks * 16) * 2);
        }

        // ---- scores: S[16q x 64key] = Q @ K^T ----
        #pragma unroll
        for (int i = 0; i < 8; i++)
            #pragma unroll
            for (int r = 0; r < 4; r++) sc[i][r] = 0.f;

        const uint32_t kB = smb + kOff + (uint32_t)s * AT_TILE_B + lmOff;
        #pragma unroll
        for (int ks = 0; ks < 4; ks++) {
            #pragma unroll
            for (int pr = 0; pr < 4; pr++) {
                uint32_t t[4];
                ldmatrix_x4(t, kB + (uint32_t)(pr * 16 * AP + ks * 16) * 2);
                uint32_t blo[2] = {t[0], t[2]}, bhi[2] = {t[1], t[3]};
                mma_fp16(sc[2*pr],     aq[ks], blo);
                mma_fp16(sc[2*pr + 1], aq[ks], bhi);
            }
        }

        // ---- scale + mask + online softmax ----
        const int kb0 = kt * 64 + tig * 2;
        float tm0 = -1e30f, tm1 = -1e30f;
        #pragma unroll
        for (int nf = 0; nf < 8; nf++) {
            const int c = kb0 + nf * 8;
            const bool z0 = (msk[c] == 0), z1 = (msk[c + 1] == 0);
            sc[nf][0] = z0 ? -1e9f : sc[nf][0] * 0.125f;
            sc[nf][1] = z1 ? -1e9f : sc[nf][1] * 0.125f;
            sc[nf][2] = z0 ? -1e9f : sc[nf][2] * 0.125f;
            sc[nf][3] = z1 ? -1e9f : sc[nf][3] * 0.125f;
            tm0 = fmaxf(tm0, fmaxf(sc[nf][0], sc[nf][1]));
            tm1 = fmaxf(tm1, fmaxf(sc[nf][2], sc[nf][3]));
        }
        tm0 = fmaxf(tm0, __shfl_xor_sync(0xffffffffu, tm0, 1));
        tm0 = fmaxf(tm0, __shfl_xor_sync(0xffffffffu, tm0, 2));
        tm1 = fmaxf(tm1, __shfl_xor_sync(0xffffffffu, tm1, 1));
        tm1 = fmaxf(tm1, __shfl_xor_sync(0xffffffffu, tm1, 2));

        const float mn0 = fmaxf(mr0, tm0), mn1 = fmaxf(mr1, tm1);
        const float al0 = __expf(mr0 - mn0), al1 = __expf(mr1 - mn1);

        float ps0 = 0.f, ps1 = 0.f;
        #pragma unroll
        for (int nf = 0; nf < 8; nf++) {
            sc[nf][0] = __expf(sc[nf][0] - mn0);
            sc[nf][1] = __expf(sc[nf][1] - mn0);
            sc[nf][2] = __expf(sc[nf][2] - mn1);
            sc[nf][3] = __expf(sc[nf][3] - mn1);
            ps0 += sc[nf][0] + sc[nf][1];
            ps1 += sc[nf][2] + sc[nf][3];
        }
        ps0 += __shfl_xor_sync(0xffffffffu, ps0, 1);
        ps0 += __shfl_xor_sync(0xffffffffu, ps0, 2);
        ps1 += __shfl_xor_sync(0xffffffffu, ps1, 1);
        ps1 += __shfl_xor_sync(0xffffffffu, ps1, 2);

        lr0 = lr0 * al0 + ps0;
        lr1 = lr1 * al1 + ps1;
        mr0 = mn0; mr1 = mn1;
        #pragma unroll
        for (int nf = 0; nf < 8; nf++) {
            O[nf][0] *= al0; O[nf][1] *= al0;
            O[nf][2] *= al1; O[nf][3] *= al1;
        }

        // ---- O += P @ V ----
        const uint32_t vB = smb + vOff + (uint32_t)s * AT_TILE_B + lmOff;
        #pragma unroll
        for (int ks = 0; ks < 4; ks++) {
            uint32_t ap[4];
            ap[0] = pack_h2(sc[2*ks][0],     sc[2*ks][1]);
            ap[1] = pack_h2(sc[2*ks][2],     sc[2*ks][3]);
            ap[2] = pack_h2(sc[2*ks + 1][0], sc[2*ks + 1][1]);
            ap[3] = pack_h2(sc[2*ks + 1][2], sc[2*ks + 1][3]);
            #pragma unroll
            for (int pv = 0; pv < 4; pv++) {
                uint32_t t[4];
                ldmatrix_x4_trans(t, vB + (uint32_t)(ks * 16 * AP + pv * 16) * 2);
                uint32_t blo[2] = {t[0], t[1]}, bhi[2] = {t[2], t[3]};
                mma_fp16(O[2*pv],     ap, blo);
                mma_fp16(O[2*pv + 1], ap, bhi);
            }
        }
        __syncthreads();
    }

    // ---- normalize + write fp16 ctx ----
    const float inv0 = 1.f / lr0, inv1 = 1.f / lr1;
    const int r0 = qt * 64 + wid * 16 + gidq;
    __half* op0 = ctxh + ((size_t)(b * S_ + r0)) * D_ + h * 64;
    __half* op1 = op0 + (size_t)8 * D_;
    #pragma unroll
    for (int nf = 0; nf < 8; nf++) {
        const int c = nf * 8 + tig * 2;
        *(uint32_t*)(op0 + c) = pack_h2(O[nf][0] * inv0, O[nf][1] * inv0);
        *(uint32_t*)(op1 + c) = pack_h2(O[nf][2] * inv1, O[nf][3] * inv1);
    }
}

// ---------------------------------------------------------------------------
// Launch
// ---------------------------------------------------------------------------
extern "C" void kernel_launch(void* const* d_in, const int* in_sizes, int n_in,
                              void* d_out, int out_size)
{
    const float* x    = (const float*)d_in[0];
    const int*   mask = (const int*)  d_in[1];
    const float* wq   = (const float*)d_in[2];
    const float* bq   = (const float*)d_in[3];
    const float* wk   = (const float*)d_in[4];
    const float* bk   = (const float*)d_in[5];
    const float* wv   = (const float*)d_in[6];
    const float* bv   = (const float*)d_in[7];
    const float* wo   = (const float*)d_in[8];
    const float* bo   = (const float*)d_in[9];
    const float* w1   = (const float*)d_in[10];
    const float* b1   = (const float*)d_in[11];
    const float* w2   = (const float*)d_in[12];
    const float* b2   = (const float*)d_in[13];
    const float* a1   = (const float*)d_in[14];
    const float* be1  = (const float*)d_in[15];
    const float* a2   = (const float*)d_in[16];
    const float* be2  = (const float*)d_in[17];
    float* out = (float*)d_out;

    __half *qh, *kh, *vh, *ctxh, *xn, *xn2, *ffh;
    __half *wqt, *wkt, *wvt, *wot, *w1t, *w2t;
    cudaGetSymbolAddress((void**)&qh,   g_qh);
    cudaGetSymbolAddress((void**)&kh,   g_kh);
    cudaGetSymbolAddress((void**)&vh,   g_vh);
    cudaGetSymbolAddress((void**)&ctxh, g_ctxh);
    cudaGetSymbolAddress((void**)&xn,   g_xn);
    cudaGetSymbolAddress((void**)&xn2,  g_xn2);
    cudaGetSymbolAddress((void**)&ffh,  g_ffh);
    cudaGetSymbolAddress((void**)&wqt,  g_wqt);
    cudaGetSymbolAddress((void**)&wkt,  g_wkt);
    cudaGetSymbolAddress((void**)&wvt,  g_wvt);
    cudaGetSymbolAddress((void**)&wot,  g_wot);
    cudaGetSymbolAddress((void**)&w1t,  g_w1t);
    cudaGetSymbolAddress((void**)&w2t,  g_w2t);

    cudaFuncSetAttribute(attn_tc_kernel, cudaFuncAttributeMaxDynamicSharedMemorySize,
                         ATTN_SMEM);
    cudaFuncSetAttribute(tc_gemm_kernel<1>, cudaFuncAttributeMaxDynamicSharedMemorySize,
                         GEMM_SMEM);
    cudaFuncSetAttribute(tc_gemm_kernel<2>, cudaFuncAttributeMaxDynamicSharedMemorySize,
                         GEMM_SMEM);
    cudaFuncSetAttribute(tc_gemm_kernel<3>, cudaFuncAttributeMaxDynamicSharedMemorySize,
                         GEMM_SMEM);

    const dim3 wblk(32, 8);
    wconv_kernel<<<dim3(D_/32,   D_/32),   wblk>>>(wq, wqt, D_,   D_);
    wconv_kernel<<<dim3(D_/32,   D_/32),   wblk>>>(wk, wkt, D_,   D_);
    wconv_kernel<<<dim3(D_/32,   D_/32),   wblk>>>(wv, wvt, D_,   D_);
    wconv_kernel<<<dim3(D_/32,   D_/32),   wblk>>>(wo, wot, D_,   D_);
    wconv_kernel<<<dim3(DFF_/32, D_/32),   wblk>>>(w1, w1t, D_,   DFF_);
    wconv_kernel<<<dim3(D_/32,   DFF_/32), wblk>>>(w2, w2t, DFF_, D_);

    // 1) pre-norm 1 -> fp16
    ln_h_kernel<<<ROWS_, 256>>>(x, a1, be1, xn);

    const dim3 gD (D_   / NT, ROWS_ / MT);   // (8, 32)
    const dim3 gFF(DFF_ / NT, ROWS_ / MT);   // (32, 32)

    // 2) Q/K/V projections -> fp16
    tc_gemm_kernel<3><<<gD, 256, GEMM_SMEM>>>(xn, wqt, bq, nullptr, nullptr, qh,
                                              ROWS_, D_, D_);
    tc_gemm_kernel<3><<<gD, 256, GEMM_SMEM>>>(xn, wkt, bk, nullptr, nullptr, kh,
                                              ROWS_, D_, D_);
    tc_gemm_kernel<3><<<gD, 256, GEMM_SMEM>>>(xn, wvt, bv, nullptr, nullptr, vh,
                                              ROWS_, D_, D_);

    // 3) tensor-core flash attention -> fp16 ctx
    attn_tc_kernel<<<dim3(S_/64, H_, B_), 128, ATTN_SMEM>>>(qh, kh, vh, mask, ctxh);

    // 4) out = x + ctx@wo + bo
    tc_gemm_kernel<2><<<gD, 256, GEMM_SMEM>>>(ctxh, wot, bo, x, out, nullptr,
                                              ROWS_, D_, D_);

    // 5) pre-norm 2 -> fp16
    ln_h_kernel<<<ROWS_, 256>>>(out, a2, be2, xn2);

    // 6) FFN up + relu -> fp16
    tc_gemm_kernel<1><<<gFF, 256, GEMM_SMEM>>>(xn2, w1t, b1, nullptr, nullptr, ffh,
                                               ROWS_, DFF_, D_);

    // 7) FFN down + residual 2 (in-place on out)
    tc_gemm_kernel<2><<<gD, 256, GEMM_SMEM>>>(ffh, w2t, b2, out, out, nullptr,
                                              ROWS_, D_, DFF_);
}